// round 14
// baseline (speedup 1.0000x reference)
#include <cuda_runtime.h>
#include <cuda_fp16.h>
#include <math.h>

// Problem constants
#define BB 2
#define SS 2048
#define DD 1024
#define HH 16
#define DKK 64
#define MM (BB * SS)

// ---------------------------------------------------------------------------
// Scratch (device globals)
// ---------------------------------------------------------------------------
__device__ __half g_Qh[BB * HH * SS * DKK];   // [B,H,S,DK] fp16
__device__ __half g_Kh[BB * HH * SS * DKK];
__device__ __half g_Vh[BB * HH * SS * DKK];
__device__ __half g_Ctxh[BB * SS * DD];       // [B,S,D] fp16
__device__ __half g_qh[MM * DD];              // fp16 inputs
__device__ __half g_kh[MM * DD];
__device__ __half g_vh[MM * DD];
__device__ __half g_wh[4][DD * DD];           // fp16 weights q,k,v,o

// ---------------------------------------------------------------------------
// helpers
// ---------------------------------------------------------------------------
__device__ __forceinline__ float ex2(float x) {
    float y;
    asm("ex2.approx.f32 %0, %1;" : "=f"(y) : "f"(x));
    return y;
}

__device__ __forceinline__ void mma_f16(float* c, const unsigned* a, const unsigned* b) {
    asm volatile("mma.sync.aligned.m16n8k16.row.col.f32.f16.f16.f32 "
        "{%0,%1,%2,%3}, {%4,%5,%6,%7}, {%8,%9}, {%0,%1,%2,%3};"
        : "+f"(c[0]), "+f"(c[1]), "+f"(c[2]), "+f"(c[3])
        : "r"(a[0]), "r"(a[1]), "r"(a[2]), "r"(a[3]), "r"(b[0]), "r"(b[1]));
}

__device__ __forceinline__ unsigned smem_u32(const void* p) {
    return (unsigned)__cvta_generic_to_shared(p);
}
__device__ __forceinline__ void ldsm_x4(unsigned* r, unsigned addr) {
    asm volatile("ldmatrix.sync.aligned.m8n8.x4.shared.b16 {%0,%1,%2,%3}, [%4];"
        : "=r"(r[0]), "=r"(r[1]), "=r"(r[2]), "=r"(r[3]) : "r"(addr));
}
__device__ __forceinline__ void ldsm_x2(unsigned* r, unsigned addr) {
    asm volatile("ldmatrix.sync.aligned.m8n8.x2.shared.b16 {%0,%1}, [%2];"
        : "=r"(r[0]), "=r"(r[1]) : "r"(addr));
}
__device__ __forceinline__ void ldsm_x2_trans(unsigned* r, unsigned addr) {
    asm volatile("ldmatrix.sync.aligned.m8n8.x2.trans.shared.b16 {%0,%1}, [%2];"
        : "=r"(r[0]), "=r"(r[1]) : "r"(addr));
}

__device__ __forceinline__ void cp_async16(void* smem_dst, const void* gmem_src) {
    unsigned s = (unsigned)__cvta_generic_to_shared(smem_dst);
    asm volatile("cp.async.cg.shared.global [%0], [%1], 16;" :: "r"(s), "l"(gmem_src));
}
__device__ __forceinline__ void cp_commit() {
    asm volatile("cp.async.commit_group;");
}
template <int N> __device__ __forceinline__ void cp_wait() {
    asm volatile("cp.async.wait_group %0;" :: "n"(N));
}

// ---------------------------------------------------------------------------
// Prepass: fp32 -> fp16 conversion (inputs q,k,v + 4 weights)
// ---------------------------------------------------------------------------
struct F2HArgs {
    const float4* src[7];
    __half*       dst[7];
    int           n8[7];
};

__global__ __launch_bounds__(256) void f2h_kernel(F2HArgs a)
{
    int z = blockIdx.z;
    const float4* s = a.src[z];
    uint4* d = (uint4*)a.dst[z];
    int n8 = a.n8[z];
    int stride = gridDim.x * blockDim.x;
    for (int i = blockIdx.x * blockDim.x + threadIdx.x; i < n8; i += stride) {
        float4 x = s[2 * i], y = s[2 * i + 1];
        __half2 h0 = __floats2half2_rn(x.x, x.y);
        __half2 h1 = __floats2half2_rn(x.z, x.w);
        __half2 h2 = __floats2half2_rn(y.x, y.y);
        __half2 h3 = __floats2half2_rn(y.z, y.w);
        uint4 o;
        o.x = *(unsigned*)&h0; o.y = *(unsigned*)&h1;
        o.z = *(unsigned*)&h2; o.w = *(unsigned*)&h3;
        d[i] = o;
    }
}

// ---------------------------------------------------------------------------
// Pipelined NT GEMM via fp16 m16n8k16 mma.sync (R11 proven config):
// BM=BN=128, BK=32 halfs, 3-stage cp.async ring, 128 thr (4 warps 2x2),
// warp tile 64x64 (4m x 8n MMAs x 2 k-steps).
// ---------------------------------------------------------------------------
#define RW 20           // row stride in 32-bit words
#define STG 3
#define KT (DD / 32)    // 32 k-tiles

struct GemmArgs {
    const __half* A[3];
    const __half* W[3];
    const float*  bias[3];
    float* C;
    int out_mode[3];
};

__global__ __launch_bounds__(128, 3) void gemm_f16_kernel(GemmArgs args)
{
    __shared__ unsigned As[STG][128 * RW];
    __shared__ unsigned Bs[STG][128 * RW];

    int z = blockIdx.z;
    const __half* __restrict__ Ain  = args.A[z];
    const __half* __restrict__ W    = args.W[z];
    const float*  __restrict__ bias = args.bias[z];
    int out_mode = args.out_mode[z];

    int tid  = threadIdx.x;
    int lane = tid & 31;
    int w    = tid >> 5;
    int wm   = w >> 1;
    int wn   = w & 1;
    int g    = lane >> 2;
    int t    = lane & 3;

    int bm = blockIdx.y * 128;
    int bn = blockIdx.x * 128;

    float c[4][8][4];
#pragma unroll
    for (int mi = 0; mi < 4; mi++)
#pragma unroll
        for (int nj = 0; nj < 8; nj++)
#pragma unroll
            for (int e = 0; e < 4; e++) c[mi][nj][e] = 0.0f;

#pragma unroll
    for (int pf = 0; pf < STG - 1; pf++) {
        int k0 = pf * 32;
#pragma unroll
        for (int it = 0; it < 4; it++) {
            int idx = it * 128 + tid;
            int row = idx >> 2;
            int ch  = idx & 3;
            cp_async16(&As[pf][row * RW + ch * 4],
                       &Ain[(size_t)(bm + row) * DD + k0 + ch * 8]);
            cp_async16(&Bs[pf][row * RW + ch * 4],
                       &W[(size_t)(bn + row) * DD + k0 + ch * 8]);
        }
        cp_commit();
    }
    cp_wait<STG - 2>();
    __syncthreads();

    for (int kt = 0; kt < KT; kt++) {
        int st = kt % STG;

        if (kt + STG - 1 < KT) {
            int ps = (kt + STG - 1) % STG;
            int k0 = (kt + STG - 1) * 32;
#pragma unroll
            for (int it = 0; it < 4; it++) {
                int idx = it * 128 + tid;
                int row = idx >> 2;
                int ch  = idx & 3;
                cp_async16(&As[ps][row * RW + ch * 4],
                           &Ain[(size_t)(bm + row) * DD + k0 + ch * 8]);
                cp_async16(&Bs[ps][row * RW + ch * 4],
                           &W[(size_t)(bn + row) * DD + k0 + ch * 8]);
            }
        }
        cp_commit();

        const unsigned* a_s = As[st];
        const unsigned* b_s = Bs[st];
#pragma unroll
        for (int ks = 0; ks < 2; ks++) {
            unsigned af[4][4], bf[8][2];
#pragma unroll
            for (int mi = 0; mi < 4; mi++) {
                int m = wm * 64 + mi * 16 + g;
                af[mi][0] = a_s[m * RW + ks * 8 + t];
                af[mi][1] = a_s[(m + 8) * RW + ks * 8 + t];
                af[mi][2] = a_s[m * RW + ks * 8 + t + 4];
                af[mi][3] = a_s[(m + 8) * RW + ks * 8 + t + 4];
            }
#pragma unroll
            for (int nj = 0; nj < 8; nj++) {
                int n = wn * 64 + nj * 8 + g;
                bf[nj][0] = b_s[n * RW + ks * 8 + t];
                bf[nj][1] = b_s[n * RW + ks * 8 + t + 4];
            }
#pragma unroll
            for (int mi = 0; mi < 4; mi++)
#pragma unroll
                for (int nj = 0; nj < 8; nj++)
                    mma_f16(c[mi][nj], af[mi], bf[nj]);
        }

        cp_wait<STG - 2>();
        __syncthreads();
    }

#pragma unroll
    for (int mi = 0; mi < 4; mi++) {
#pragma unroll
        for (int nj = 0; nj < 8; nj++) {
            int m = bm + wm * 64 + mi * 16 + g;
            int n = bn + wn * 64 + nj * 8 + 2 * t;
            float b0 = bias[n], b1 = bias[n + 1];
            if (out_mode == 0) {
                *(float2*)&args.C[(size_t)m * DD + n] =
                    make_float2(c[mi][nj][0] + b0, c[mi][nj][1] + b1);
                *(float2*)&args.C[(size_t)(m + 8) * DD + n] =
                    make_float2(c[mi][nj][2] + b0, c[mi][nj][3] + b1);
            } else {
                __half2 v0 = __floats2half2_rn(c[mi][nj][0] + b0, c[mi][nj][1] + b1);
                __half2 v1 = __floats2half2_rn(c[mi][nj][2] + b0, c[mi][nj][3] + b1);
                int b  = m >> 11;
                int s  = m & (SS - 1);
                int h  = n >> 6;
                int dk = n & (DKK - 1);
                __half* dst = (out_mode == 1) ? g_Qh : (out_mode == 2) ? g_Kh : g_Vh;
                size_t base = (((size_t)(b * HH + h)) * SS) * DKK + dk;
                *(__half2*)&dst[base + (size_t)s * DKK]  = v0;
                int s1 = (m + 8) & (SS - 1);
                *(__half2*)&dst[base + (size_t)s1 * DKK] = v1;
            }
        }
    }
}

// ---------------------------------------------------------------------------
// Causal flash attention via fp16 m16n8k16 mma.sync (R11 winner, BQ=64),
// with K fragments via ldmatrix.x2 (was: 2 scalar LDS per fragment).
// grid=(S/64, B*H), 128 thr (4 warps); warp owns 16 Q rows.
// ---------------------------------------------------------------------------
#define SCALE_LOG2E 0.1803368801111244f   // (1/sqrt(64)) * log2(e)
#define AR 72                              // attention smem row stride (halfs)

__global__ __launch_bounds__(128) void attn_f16_kernel()
{
    __shared__ __half QPs[64][AR];
    __shared__ __half Ks[2][64][AR];
    __shared__ __half Vs[2][64][AR];

    int tid  = threadIdx.x;
    int lane = tid & 31;
    int w    = tid >> 5;
    int g    = lane >> 2;
    int t    = lane & 3;
    int wrow = w * 16;

    int qb = gridDim.x - 1 - blockIdx.x;
    int bh = blockIdx.y;
    int b  = bh >> 4;
    int h  = bh & (HH - 1);
    size_t head = (size_t)bh * SS * DKK;

    // ldmatrix per-lane base addresses
    int qrow = wrow + (lane & 7) + ((lane >> 3) & 1) * 8;
    int qcol = (lane >> 4) * 8;
    unsigned qp_lane = smem_u32(&QPs[qrow][qcol]);
    // K x2 (non-trans): lanes 0-7 -> rows (lane&7) col 0; lanes 8-15 -> col 8
    int krow = lane & 7;
    int kcol = ((lane >> 3) & 1) * 8;
    unsigned k_lane0 = smem_u32(&Ks[0][krow][kcol]);
    unsigned k_lane1 = smem_u32(&Ks[1][krow][kcol]);
    // V x2.trans: lanes 0-15 = rows (lane&15)
    unsigned v_lane0 = smem_u32(&Vs[0][lane & 15][0]);
    unsigned v_lane1 = smem_u32(&Vs[1][lane & 15][0]);

#pragma unroll
    for (int it = 0; it < 4; it++) {
        int i  = it * 128 + tid;
        int r  = i >> 3;
        int c8 = (i & 7) << 3;
        *(uint4*)&QPs[r][c8] =
            *(const uint4*)&g_Qh[head + (size_t)(qb * 64 + r) * DKK + c8];
    }

#pragma unroll
    for (int it = 0; it < 4; it++) {
        int i  = it * 128 + tid;
        int r  = i >> 3;
        int c8 = (i & 7) << 3;
        size_t gi = head + (size_t)r * DKK + c8;
        cp_async16(&Ks[0][r][c8], &g_Kh[gi]);
        cp_async16(&Vs[0][r][c8], &g_Vh[gi]);
    }
    cp_commit();
    __syncthreads();

    unsigned qf[4][4];
#pragma unroll
    for (int ks = 0; ks < 4; ks++)
        ldsm_x4(qf[ks], qp_lane + ks * 32);

    float o[8][4];
#pragma unroll
    for (int nj = 0; nj < 8; nj++)
#pragma unroll
        for (int e = 0; e < 4; e++) o[nj][e] = 0.0f;
    float m0 = -1e30f, m1 = -1e30f, l0 = 0.0f, l1 = 0.0f;

    for (int j = 0; j <= qb; j++) {
        int cur = j & 1;
        __syncthreads();

        if (j < qb) {
            int nxt = (j + 1) & 1;
#pragma unroll
            for (int it = 0; it < 4; it++) {
                int i  = it * 128 + tid;
                int r  = i >> 3;
                int c8 = (i & 7) << 3;
                size_t gi = head + (size_t)((j + 1) * 64 + r) * DKK + c8;
                cp_async16(&Ks[nxt][r][c8], &g_Kh[gi]);
                cp_async16(&Vs[nxt][r][c8], &g_Vh[gi]);
            }
        }
        cp_commit();
        cp_wait<1>();
        __syncthreads();

        // ---- S = Q @ K^T (K frags via ldmatrix.x2) ----
        float s[8][4];
#pragma unroll
        for (int nj = 0; nj < 8; nj++)
#pragma unroll
            for (int e = 0; e < 4; e++) s[nj][e] = 0.0f;

        unsigned k_base = cur ? k_lane1 : k_lane0;
#pragma unroll
        for (int ks = 0; ks < 4; ks++) {
#pragma unroll
            for (int nj = 0; nj < 8; nj++) {
                unsigned bf[2];
                ldsm_x2(bf, k_base + (unsigned)(nj * 8 * AR + ks * 16) * 2u);
                mma_f16(s[nj], qf[ks], bf);
            }
        }

#pragma unroll
        for (int nj = 0; nj < 8; nj++)
#pragma unroll
            for (int e = 0; e < 4; e++) s[nj][e] *= SCALE_LOG2E;

        if (j == qb) {
#pragma unroll
            for (int nj = 0; nj < 8; nj++) {
                int c0 = nj * 8 + 2 * t;
                if (c0     > wrow + g)     s[nj][0] = -1e30f;
                if (c0 + 1 > wrow + g)     s[nj][1] = -1e30f;
                if (c0     > wrow + g + 8) s[nj][2] = -1e30f;
                if (c0 + 1 > wrow + g + 8) s[nj][3] = -1e30f;
            }
        }

        float mx0 = -1e30f, mx1 = -1e30f;
#pragma unroll
        for (int nj = 0; nj < 8; nj++) {
            mx0 = fmaxf(mx0, fmaxf(s[nj][0], s[nj][1]));
            mx1 = fmaxf(mx1, fmaxf(s[nj][2], s[nj][3]));
        }
        mx0 = fmaxf(mx0, __shfl_xor_sync(0xffffffffu, mx0, 1));
        mx0 = fmaxf(mx0, __shfl_xor_sync(0xffffffffu, mx0, 2));
        mx1 = fmaxf(mx1, __shfl_xor_sync(0xffffffffu, mx1, 1));
        mx1 = fmaxf(mx1, __shfl_xor_sync(0xffffffffu, mx1, 2));

        float m0n = fmaxf(m0, mx0), m1n = fmaxf(m1, mx1);
        float a0 = ex2(m0 - m0n),   a1 = ex2(m1 - m1n);
        m0 = m0n; m1 = m1n;

        float rs0 = 0.0f, rs1 = 0.0f;
#pragma unroll
        for (int nj = 0; nj < 8; nj++) {
            float p;
            p = ex2(s[nj][0] - m0n); rs0 += p; s[nj][0] = p;
            p = ex2(s[nj][1] - m0n); rs0 += p; s[nj][1] = p;
            p = ex2(s[nj][2] - m1n); rs1 += p; s[nj][2] = p;
            p = ex2(s[nj][3] - m1n); rs1 += p; s[nj][3] = p;
        }
        rs0 += __shfl_xor_sync(0xffffffffu, rs0, 1);
        rs0 += __shfl_xor_sync(0xffffffffu, rs0, 2);
        rs1 += __shfl_xor_sync(0xffffffffu, rs1, 1);
        rs1 += __shfl_xor_sync(0xffffffffu, rs1, 2);

        l0 = l0 * a0 + rs0;
        l1 = l1 * a1 + rs1;
#pragma unroll
        for (int nj = 0; nj < 8; nj++) {
            o[nj][0] *= a0; o[nj][1] *= a0;
            o[nj][2] *= a1; o[nj][3] *= a1;
        }

#pragma unroll
        for (int nj = 0; nj < 8; nj++) {
            int cc = nj * 8 + 2 * t;
            *(__half2*)&QPs[wrow + g][cc]     = __floats2half2_rn(s[nj][0], s[nj][1]);
            *(__half2*)&QPs[wrow + g + 8][cc] = __floats2half2_rn(s[nj][2], s[nj][3]);
        }
        __syncwarp();

        unsigned v_base = cur ? v_lane1 : v_lane0;
#pragma unroll
        for (int ks = 0; ks < 4; ks++) {
            unsigned pf[4];
            ldsm_x4(pf, qp_lane + ks * 32);
#pragma unroll
            for (int nj = 0; nj < 8; nj++) {
                unsigned vf[2];
                ldsm_x2_trans(vf, v_base + (unsigned)(ks * 16 * AR + nj * 8) * 2u);
                mma_f16(o[nj], pf, vf);
            }
        }
    }

    float inv0 = 1.0f / l0, inv1 = 1.0f / l1;
    int row0 = qb * 64 + wrow + g;
    size_t base0 = ((size_t)(b * SS + row0)) * DD + h * 64;
    size_t base1 = base0 + (size_t)8 * DD;
#pragma unroll
    for (int nj = 0; nj < 8; nj++) {
        int cc = nj * 8 + 2 * t;
        *(__half2*)&g_Ctxh[base0 + cc] = __floats2half2_rn(o[nj][0] * inv0, o[nj][1] * inv0);
        *(__half2*)&g_Ctxh[base1 + cc] = __floats2half2_rn(o[nj][2] * inv1, o[nj][3] * inv1);
    }
}

// ---------------------------------------------------------------------------
// kernel_launch
// ---------------------------------------------------------------------------
extern "C" void kernel_launch(void* const* d_in, const int* in_sizes, int n_in,
                              void* d_out, int out_size)
{
    const float* q    = (const float*)d_in[0];
    const float* k    = (const float*)d_in[1];
    const float* v    = (const float*)d_in[2];
    const float* wq_w = (const float*)d_in[4];
    const float* wq_b = (const float*)d_in[5];
    const float* wk_w = (const float*)d_in[6];
    const float* wk_b = (const float*)d_in[7];
    const float* wv_w = (const float*)d_in[8];
    const float* wv_b = (const float*)d_in[9];
    const float* wo_w = (const float*)d_in[10];
    const float* wo_b = (const float*)d_in[11];
    float* out = (float*)d_out;

    void *p_qh, *p_kh, *p_vh, *p_wh, *p_ctxh;
    cudaGetSymbolAddress(&p_qh, g_qh);
    cudaGetSymbolAddress(&p_kh, g_kh);
    cudaGetSymbolAddress(&p_vh, g_vh);
    cudaGetSymbolAddress(&p_wh, g_wh);
    cudaGetSymbolAddress(&p_ctxh, g_Ctxh);
    __half* w0 = (__half*)p_wh;
    __half* w1 = w0 + DD * DD;
    __half* w2 = w0 + 2 * DD * DD;
    __half* w3 = w0 + 3 * DD * DD;

    // prepass: convert inputs + weights to fp16
    F2HArgs fa;
    fa.src[0] = (const float4*)q;    fa.dst[0] = (__half*)p_qh; fa.n8[0] = MM * DD / 8;
    fa.src[1] = (const float4*)k;    fa.dst[1] = (__half*)p_kh; fa.n8[1] = MM * DD / 8;
    fa.src[2] = (const float4*)v;    fa.dst[2] = (__half*)p_vh; fa.n8[2] = MM * DD / 8;
    fa.src[3] = (const float4*)wq_w; fa.dst[3] = w0;            fa.n8[3] = DD * DD / 8;
    fa.src[4] = (const float4*)wk_w; fa.dst[4] = w1;            fa.n8[4] = DD * DD / 8;
    fa.src[5] = (const float4*)wv_w; fa.dst[5] = w2;            fa.n8[5] = DD * DD / 8;
    fa.src[6] = (const float4*)wo_w; fa.dst[6] = w3;            fa.n8[6] = DD * DD / 8;
    f2h_kernel<<<dim3(128, 1, 7), 256>>>(fa);

    // fused QKV projections
    GemmArgs qkv;
    qkv.A[0] = (const __half*)p_qh; qkv.A[1] = (const __half*)p_kh; qkv.A[2] = (const __half*)p_vh;
    qkv.W[0] = w0; qkv.W[1] = w1; qkv.W[2] = w2;
    qkv.bias[0] = wq_b; qkv.bias[1] = wk_b; qkv.bias[2] = wv_b;
    qkv.C = nullptr;
    qkv.out_mode[0] = 1; qkv.out_mode[1] = 2; qkv.out_mode[2] = 3;
    gemm_f16_kernel<<<dim3(DD / 128, MM / 128, 3), 128>>>(qkv);

    // attention (BQ=64)
    attn_f16_kernel<<<dim3(SS / 64, BB * HH), 128>>>();

    // output projection
    GemmArgs og;
    og.A[0] = (const __half*)p_ctxh; og.A[1] = og.A[0]; og.A[2] = og.A[0];
    og.W[0] = w3; og.W[1] = w3; og.W[2] = w3;
    og.bias[0] = wo_b; og.bias[1] = wo_b; og.bias[2] = wo_b;
    og.C = out;
    og.out_mode[0] = 0; og.out_mode[1] = 0; og.out_mode[2] = 0;
    gemm_f16_kernel<<<dim3(DD / 128, MM / 128, 1), 128>>>(og);
}

// round 15
// speedup vs baseline: 1.0969x; 1.0969x over previous
#include <cuda_runtime.h>
#include <cuda_fp16.h>
#include <math.h>

// Problem constants
#define BB 2
#define SS 2048
#define DD 1024
#define HH 16
#define DKK 64
#define MM (BB * SS)

// ---------------------------------------------------------------------------
// Scratch (device globals)
// ---------------------------------------------------------------------------
__device__ __half g_Qh[BB * HH * SS * DKK];   // [B,H,S,DK] fp16
__device__ __half g_Kh[BB * HH * SS * DKK];
__device__ __half g_Vh[BB * HH * SS * DKK];
__device__ __half g_Ctxh[BB * SS * DD];       // [B,S,D] fp16
__device__ __half g_qh[MM * DD];              // fp16 inputs
__device__ __half g_kh[MM * DD];
__device__ __half g_vh[MM * DD];
__device__ __half g_wh[4][DD * DD];           // fp16 weights q,k,v,o

// ---------------------------------------------------------------------------
// helpers
// ---------------------------------------------------------------------------
__device__ __forceinline__ float ex2(float x) {
    float y;
    asm("ex2.approx.f32 %0, %1;" : "=f"(y) : "f"(x));
    return y;
}

__device__ __forceinline__ unsigned packh2(float a, float b) {
    __half2 h = __floats2half2_rn(a, b);
    return *(unsigned*)&h;
}

__device__ __forceinline__ void mma_f16(float* c, const unsigned* a, const unsigned* b) {
    asm volatile("mma.sync.aligned.m16n8k16.row.col.f32.f16.f16.f32 "
        "{%0,%1,%2,%3}, {%4,%5,%6,%7}, {%8,%9}, {%0,%1,%2,%3};"
        : "+f"(c[0]), "+f"(c[1]), "+f"(c[2]), "+f"(c[3])
        : "r"(a[0]), "r"(a[1]), "r"(a[2]), "r"(a[3]), "r"(b[0]), "r"(b[1]));
}

__device__ __forceinline__ unsigned smem_u32(const void* p) {
    return (unsigned)__cvta_generic_to_shared(p);
}
__device__ __forceinline__ void ldsm_x4(unsigned* r, unsigned addr) {
    asm volatile("ldmatrix.sync.aligned.m8n8.x4.shared.b16 {%0,%1,%2,%3}, [%4];"
        : "=r"(r[0]), "=r"(r[1]), "=r"(r[2]), "=r"(r[3]) : "r"(addr));
}
__device__ __forceinline__ void ldsm_x4_trans(unsigned* r, unsigned addr) {
    asm volatile("ldmatrix.sync.aligned.m8n8.x4.trans.shared.b16 {%0,%1,%2,%3}, [%4];"
        : "=r"(r[0]), "=r"(r[1]), "=r"(r[2]), "=r"(r[3]) : "r"(addr));
}

__device__ __forceinline__ void cp_async16(void* smem_dst, const void* gmem_src) {
    unsigned s = (unsigned)__cvta_generic_to_shared(smem_dst);
    asm volatile("cp.async.cg.shared.global [%0], [%1], 16;" :: "r"(s), "l"(gmem_src));
}
__device__ __forceinline__ void cp_commit() {
    asm volatile("cp.async.commit_group;");
}
template <int N> __device__ __forceinline__ void cp_wait() {
    asm volatile("cp.async.wait_group %0;" :: "n"(N));
}

// ---------------------------------------------------------------------------
// Prepass: fp32 -> fp16 conversion (inputs q,k,v + 4 weights)
// ---------------------------------------------------------------------------
struct F2HArgs {
    const float4* src[7];
    __half*       dst[7];
    int           n8[7];
};

__global__ __launch_bounds__(256) void f2h_kernel(F2HArgs a)
{
    int z = blockIdx.z;
    const float4* s = a.src[z];
    uint4* d = (uint4*)a.dst[z];
    int n8 = a.n8[z];
    int stride = gridDim.x * blockDim.x;
    for (int i = blockIdx.x * blockDim.x + threadIdx.x; i < n8; i += stride) {
        float4 x = s[2 * i], y = s[2 * i + 1];
        uint4 o;
        o.x = packh2(x.x, x.y); o.y = packh2(x.z, x.w);
        o.z = packh2(y.x, y.y); o.w = packh2(y.z, y.w);
        d[i] = o;
    }
}

// ---------------------------------------------------------------------------
// Pipelined NT GEMM via fp16 m16n8k16 mma.sync (R11 geometry + ldsm.x4):
// BM=BN=128, BK=32 halfs, 3-stage cp.async ring, 128 thr (4 warps 2x2),
// warp tile 64x64 (4m x 8n MMAs x 2 k-steps). Fragments via ldmatrix.x4.
// ---------------------------------------------------------------------------
#define RW 20           // row stride in 32-bit words (16B-aligned rows: 80B)
#define STG 3
#define KT (DD / 32)    // 32 k-tiles

struct GemmArgs {
    const __half* A[3];
    const __half* W[3];
    const float*  bias[3];
    float* C;
    int out_mode[3];
};

__global__ __launch_bounds__(128, 3) void gemm_f16_kernel(GemmArgs args)
{
    __shared__ unsigned As[STG][128 * RW];
    __shared__ unsigned Bs[STG][128 * RW];

    int z = blockIdx.z;
    const __half* __restrict__ Ain  = args.A[z];
    const __half* __restrict__ W    = args.W[z];
    const float*  __restrict__ bias = args.bias[z];
    int out_mode = args.out_mode[z];

    int tid  = threadIdx.x;
    int lane = tid & 31;
    int w    = tid >> 5;
    int wm   = w >> 1;
    int wn   = w & 1;
    int g    = lane >> 2;
    int t    = lane & 3;

    int bm = blockIdx.y * 128;
    int bn = blockIdx.x * 128;

    // ldmatrix per-lane base word offsets
    // A x4: lanes 0-7 rows m..m+7 col0 | 8-15 rows m+8..15 col0 | 16-23 rows m..7 col8 | 24-31 m+8..15 col8
    int a_off = (wm * 64 + (lane & 15)) * RW + ((lane >> 4) << 2);
    // B x4 (2 nj per op): lanes 0-7 rows n..n+7 col0 | 8-15 same rows col8 | 16-23 rows n+8..15 col0 | 24-31 col8
    int b_off = (wn * 64 + (lane & 7) + ((lane >> 4) << 3)) * RW + (((lane >> 3) & 1) << 2);

    unsigned a_smem0 = smem_u32(&As[0][0]);
    unsigned b_smem0 = smem_u32(&Bs[0][0]);

    float c[4][8][4];
#pragma unroll
    for (int mi = 0; mi < 4; mi++)
#pragma unroll
        for (int nj = 0; nj < 8; nj++)
#pragma unroll
            for (int e = 0; e < 4; e++) c[mi][nj][e] = 0.0f;

#pragma unroll
    for (int pf = 0; pf < STG - 1; pf++) {
        int k0 = pf * 32;
#pragma unroll
        for (int it = 0; it < 4; it++) {
            int idx = it * 128 + tid;
            int row = idx >> 2;
            int ch  = idx & 3;
            cp_async16(&As[pf][row * RW + ch * 4],
                       &Ain[(size_t)(bm + row) * DD + k0 + ch * 8]);
            cp_async16(&Bs[pf][row * RW + ch * 4],
                       &W[(size_t)(bn + row) * DD + k0 + ch * 8]);
        }
        cp_commit();
    }
    cp_wait<STG - 2>();
    __syncthreads();

    for (int kt = 0; kt < KT; kt++) {
        int st = kt % STG;

        if (kt + STG - 1 < KT) {
            int ps = (kt + STG - 1) % STG;
            int k0 = (kt + STG - 1) * 32;
#pragma unroll
            for (int it = 0; it < 4; it++) {
                int idx = it * 128 + tid;
                int row = idx >> 2;
                int ch  = idx & 3;
                cp_async16(&As[ps][row * RW + ch * 4],
                           &Ain[(size_t)(bm + row) * DD + k0 + ch * 8]);
                cp_async16(&Bs[ps][row * RW + ch * 4],
                           &W[(size_t)(bn + row) * DD + k0 + ch * 8]);
            }
        }
        cp_commit();

        unsigned a_base = a_smem0 + (unsigned)(st * 128 * RW) * 4u;
        unsigned b_base = b_smem0 + (unsigned)(st * 128 * RW) * 4u;
#pragma unroll
        for (int ks = 0; ks < 2; ks++) {
            unsigned af[4][4];
#pragma unroll
            for (int mi = 0; mi < 4; mi++)
                ldsm_x4(af[mi], a_base + (unsigned)(a_off + mi * 16 * RW + ks * 8) * 4u);
#pragma unroll
            for (int njp = 0; njp < 4; njp++) {
                unsigned bf4[4];
                ldsm_x4(bf4, b_base + (unsigned)(b_off + njp * 16 * RW + ks * 8) * 4u);
#pragma unroll
                for (int mi = 0; mi < 4; mi++) {
                    mma_f16(c[mi][2 * njp],     af[mi], bf4);
                    mma_f16(c[mi][2 * njp + 1], af[mi], bf4 + 2);
                }
            }
        }

        cp_wait<STG - 2>();
        __syncthreads();
    }

#pragma unroll
    for (int mi = 0; mi < 4; mi++) {
#pragma unroll
        for (int nj = 0; nj < 8; nj++) {
            int m = bm + wm * 64 + mi * 16 + g;
            int n = bn + wn * 64 + nj * 8 + 2 * t;
            float b0 = bias[n], b1 = bias[n + 1];
            if (out_mode == 0) {
                *(float2*)&args.C[(size_t)m * DD + n] =
                    make_float2(c[mi][nj][0] + b0, c[mi][nj][1] + b1);
                *(float2*)&args.C[(size_t)(m + 8) * DD + n] =
                    make_float2(c[mi][nj][2] + b0, c[mi][nj][3] + b1);
            } else {
                __half2 v0 = __floats2half2_rn(c[mi][nj][0] + b0, c[mi][nj][1] + b1);
                __half2 v1 = __floats2half2_rn(c[mi][nj][2] + b0, c[mi][nj][3] + b1);
                int b  = m >> 11;
                int s  = m & (SS - 1);
                int h  = n >> 6;
                int dk = n & (DKK - 1);
                __half* dst = (out_mode == 1) ? g_Qh : (out_mode == 2) ? g_Kh : g_Vh;
                size_t base = (((size_t)(b * HH + h)) * SS) * DKK + dk;
                *(__half2*)&dst[base + (size_t)s * DKK]  = v0;
                int s1 = (m + 8) & (SS - 1);
                *(__half2*)&dst[base + (size_t)s1 * DKK] = v1;
            }
        }
    }
}

// ---------------------------------------------------------------------------
// Causal flash attention, fp16 MMA, BQ=64, register-direct P reuse:
// S-accumulator fragments are repacked in registers as the A operand of P@V
// (no P smem round-trip). K frags via ldmatrix.x4 (2 nj per op), V via
// ldmatrix.x4.trans (2 nj per op).
// ---------------------------------------------------------------------------
#define SCALE_LOG2E 0.1803368801111244f   // (1/sqrt(64)) * log2(e)
#define AR 72                              // smem row stride (halfs), 144B

__global__ __launch_bounds__(128) void attn_f16_kernel()
{
    __shared__ __half Qs[64][AR];         // Q staging only
    __shared__ __half Ks[2][64][AR];
    __shared__ __half Vs[2][64][AR];

    int tid  = threadIdx.x;
    int lane = tid & 31;
    int w    = tid >> 5;
    int g    = lane >> 2;
    int t    = lane & 3;
    int wrow = w * 16;

    int qb = gridDim.x - 1 - blockIdx.x;  // heavy blocks first
    int bh = blockIdx.y;
    int b  = bh >> 4;
    int h  = bh & (HH - 1);
    size_t head = (size_t)bh * SS * DKK;

    // per-lane ldmatrix bases
    int qrow = wrow + (lane & 7) + ((lane >> 3) & 1) * 8;
    int qcol = (lane >> 4) * 8;
    unsigned q_lane = smem_u32(&Qs[qrow][qcol]);
    // K x4: lanes 0-7 row(l&7) col0 | 8-15 row(l&7) col8 | 16-23 row+8 col0 | 24-31 row+8 col8
    int krow = (lane & 7) + ((lane >> 4) << 3);
    int kcol = ((lane >> 3) & 1) << 3;
    unsigned k_lane0 = smem_u32(&Ks[0][krow][kcol]);
    unsigned k_lane1 = smem_u32(&Ks[1][krow][kcol]);
    // V x4 trans: lanes 0-15 rows(l&15) col0 | 16-31 rows(l&15) col8
    int vrow = lane & 15;
    int vcol = (lane >> 4) << 3;
    unsigned v_lane0 = smem_u32(&Vs[0][vrow][vcol]);
    unsigned v_lane1 = smem_u32(&Vs[1][vrow][vcol]);

    // ---- stage Q tile [64][64] halfs ----
#pragma unroll
    for (int it = 0; it < 4; it++) {
        int i  = it * 128 + tid;
        int r  = i >> 3;
        int c8 = (i & 7) << 3;
        *(uint4*)&Qs[r][c8] =
            *(const uint4*)&g_Qh[head + (size_t)(qb * 64 + r) * DKK + c8];
    }

    // ---- prefetch K/V tile 0 ----
#pragma unroll
    for (int it = 0; it < 4; it++) {
        int i  = it * 128 + tid;
        int r  = i >> 3;
        int c8 = (i & 7) << 3;
        size_t gi = head + (size_t)r * DKK + c8;
        cp_async16(&Ks[0][r][c8], &g_Kh[gi]);
        cp_async16(&Vs[0][r][c8], &g_Vh[gi]);
    }
    cp_commit();
    __syncthreads();

    // ---- Q fragments (4 k-steps of 16) ----
    unsigned qf[4][4];
#pragma unroll
    for (int ks = 0; ks < 4; ks++)
        ldsm_x4(qf[ks], q_lane + ks * 32);

    float o[8][4];
#pragma unroll
    for (int nj = 0; nj < 8; nj++)
#pragma unroll
        for (int e = 0; e < 4; e++) o[nj][e] = 0.0f;
    float m0 = -1e30f, m1 = -1e30f, l0 = 0.0f, l1 = 0.0f;

    for (int j = 0; j <= qb; j++) {
        int cur = j & 1;
        __syncthreads();

        if (j < qb) {
            int nxt = (j + 1) & 1;
#pragma unroll
            for (int it = 0; it < 4; it++) {
                int i  = it * 128 + tid;
                int r  = i >> 3;
                int c8 = (i & 7) << 3;
                size_t gi = head + (size_t)((j + 1) * 64 + r) * DKK + c8;
                cp_async16(&Ks[nxt][r][c8], &g_Kh[gi]);
                cp_async16(&Vs[nxt][r][c8], &g_Vh[gi]);
            }
        }
        cp_commit();
        cp_wait<1>();
        __syncthreads();

        // ---- S = Q @ K^T (K frags via ldmatrix.x4, 2 nj per op) ----
        float s[8][4];
#pragma unroll
        for (int nj = 0; nj < 8; nj++)
#pragma unroll
            for (int e = 0; e < 4; e++) s[nj][e] = 0.0f;

        unsigned k_base = cur ? k_lane1 : k_lane0;
#pragma unroll
        for (int ks = 0; ks < 4; ks++) {
#pragma unroll
            for (int njp = 0; njp < 4; njp++) {
                unsigned bf4[4];
                ldsm_x4(bf4, k_base + (unsigned)(njp * 16 * AR + ks * 16) * 2u);
                mma_f16(s[2 * njp],     qf[ks], bf4);
                mma_f16(s[2 * njp + 1], qf[ks], bf4 + 2);
            }
        }

#pragma unroll
        for (int nj = 0; nj < 8; nj++)
#pragma unroll
            for (int e = 0; e < 4; e++) s[nj][e] *= SCALE_LOG2E;

        if (j == qb) {  // diagonal tile causal mask (local coords)
#pragma unroll
            for (int nj = 0; nj < 8; nj++) {
                int c0 = nj * 8 + 2 * t;
                if (c0     > wrow + g)     s[nj][0] = -1e30f;
                if (c0 + 1 > wrow + g)     s[nj][1] = -1e30f;
                if (c0     > wrow + g + 8) s[nj][2] = -1e30f;
                if (c0 + 1 > wrow + g + 8) s[nj][3] = -1e30f;
            }
        }

        float mx0 = -1e30f, mx1 = -1e30f;
#pragma unroll
        for (int nj = 0; nj < 8; nj++) {
            mx0 = fmaxf(mx0, fmaxf(s[nj][0], s[nj][1]));
            mx1 = fmaxf(mx1, fmaxf(s[nj][2], s[nj][3]));
        }
        mx0 = fmaxf(mx0, __shfl_xor_sync(0xffffffffu, mx0, 1));
        mx0 = fmaxf(mx0, __shfl_xor_sync(0xffffffffu, mx0, 2));
        mx1 = fmaxf(mx1, __shfl_xor_sync(0xffffffffu, mx1, 1));
        mx1 = fmaxf(mx1, __shfl_xor_sync(0xffffffffu, mx1, 2));

        float m0n = fmaxf(m0, mx0), m1n = fmaxf(m1, mx1);
        float a0 = ex2(m0 - m0n),   a1 = ex2(m1 - m1n);
        m0 = m0n; m1 = m1n;

        float rs0 = 0.0f, rs1 = 0.0f;
#pragma unroll
        for (int nj = 0; nj < 8; nj++) {
            float p;
            p = ex2(s[nj][0] - m0n); rs0 += p; s[nj][0] = p;
            p = ex2(s[nj][1] - m0n); rs0 += p; s[nj][1] = p;
            p = ex2(s[nj][2] - m1n); rs1 += p; s[nj][2] = p;
            p = ex2(s[nj][3] - m1n); rs1 += p; s[nj][3] = p;
        }
        rs0 += __shfl_xor_sync(0xffffffffu, rs0, 1);
        rs0 += __shfl_xor_sync(0xffffffffu, rs0, 2);
        rs1 += __shfl_xor_sync(0xffffffffu, rs1, 1);
        rs1 += __shfl_xor_sync(0xffffffffu, rs1, 2);

        l0 = l0 * a0 + rs0;
        l1 = l1 * a1 + rs1;
#pragma unroll
        for (int nj = 0; nj < 8; nj++) {
            o[nj][0] *= a0; o[nj][1] *= a0;
            o[nj][2] *= a1; o[nj][3] *= a1;
        }

        // ---- O += P @ V : P fragments built directly from s registers ----
        unsigned v_base = cur ? v_lane1 : v_lane0;
#pragma unroll
        for (int ks = 0; ks < 4; ks++) {
            unsigned pf[4];
            pf[0] = packh2(s[2 * ks][0],     s[2 * ks][1]);
            pf[1] = packh2(s[2 * ks][2],     s[2 * ks][3]);
            pf[2] = packh2(s[2 * ks + 1][0], s[2 * ks + 1][1]);
            pf[3] = packh2(s[2 * ks + 1][2], s[2 * ks + 1][3]);
#pragma unroll
            for (int njp = 0; njp < 4; njp++) {
                unsigned vf4[4];
                ldsm_x4_trans(vf4, v_base + (unsigned)(ks * 16 * AR + njp * 16) * 2u);
                mma_f16(o[2 * njp],     pf, vf4);
                mma_f16(o[2 * njp + 1], pf, vf4 + 2);
            }
        }
    }

    // ---- epilogue: normalize + fp16 (out-proj consumes these) ----
    float inv0 = 1.0f / l0, inv1 = 1.0f / l1;
    int row0 = qb * 64 + wrow + g;
    size_t base0 = ((size_t)(b * SS + row0)) * DD + h * 64;
    size_t base1 = base0 + (size_t)8 * DD;
#pragma unroll
    for (int nj = 0; nj < 8; nj++) {
        int cc = nj * 8 + 2 * t;
        *(__half2*)&g_Ctxh[base0 + cc] = __floats2half2_rn(o[nj][0] * inv0, o[nj][1] * inv0);
        *(__half2*)&g_Ctxh[base1 + cc] = __floats2half2_rn(o[nj][2] * inv1, o[nj][3] * inv1);
    }
}

// ---------------------------------------------------------------------------
// kernel_launch
// ---------------------------------------------------------------------------
extern "C" void kernel_launch(void* const* d_in, const int* in_sizes, int n_in,
                              void* d_out, int out_size)
{
    const float* q    = (const float*)d_in[0];
    const float* k    = (const float*)d_in[1];
    const float* v    = (const float*)d_in[2];
    const float* wq_w = (const float*)d_in[4];
    const float* wq_b = (const float*)d_in[5];
    const float* wk_w = (const float*)d_in[6];
    const float* wk_b = (const float*)d_in[7];
    const float* wv_w = (const float*)d_in[8];
    const float* wv_b = (const float*)d_in[9];
    const float* wo_w = (const float*)d_in[10];
    const float* wo_b = (const float*)d_in[11];
    float* out = (float*)d_out;

    void *p_qh, *p_kh, *p_vh, *p_wh, *p_ctxh;
    cudaGetSymbolAddress(&p_qh, g_qh);
    cudaGetSymbolAddress(&p_kh, g_kh);
    cudaGetSymbolAddress(&p_vh, g_vh);
    cudaGetSymbolAddress(&p_wh, g_wh);
    cudaGetSymbolAddress(&p_ctxh, g_Ctxh);
    __half* w0 = (__half*)p_wh;
    __half* w1 = w0 + DD * DD;
    __half* w2 = w0 + 2 * DD * DD;
    __half* w3 = w0 + 3 * DD * DD;

    // prepass: convert inputs + weights to fp16
    F2HArgs fa;
    fa.src[0] = (const float4*)q;    fa.dst[0] = (__half*)p_qh; fa.n8[0] = MM * DD / 8;
    fa.src[1] = (const float4*)k;    fa.dst[1] = (__half*)p_kh; fa.n8[1] = MM * DD / 8;
    fa.src[2] = (const float4*)v;    fa.dst[2] = (__half*)p_vh; fa.n8[2] = MM * DD / 8;
    fa.src[3] = (const float4*)wq_w; fa.dst[3] = w0;            fa.n8[3] = DD * DD / 8;
    fa.src[4] = (const float4*)wk_w; fa.dst[4] = w1;            fa.n8[4] = DD * DD / 8;
    fa.src[5] = (const float4*)wv_w; fa.dst[5] = w2;            fa.n8[5] = DD * DD / 8;
    fa.src[6] = (const float4*)wo_w; fa.dst[6] = w3;            fa.n8[6] = DD * DD / 8;
    f2h_kernel<<<dim3(128, 1, 7), 256>>>(fa);

    // fused QKV projections
    GemmArgs qkv;
    qkv.A[0] = (const __half*)p_qh; qkv.A[1] = (const __half*)p_kh; qkv.A[2] = (const __half*)p_vh;
    qkv.W[0] = w0; qkv.W[1] = w1; qkv.W[2] = w2;
    qkv.bias[0] = wq_b; qkv.bias[1] = wk_b; qkv.bias[2] = wv_b;
    qkv.C = nullptr;
    qkv.out_mode[0] = 1; qkv.out_mode[1] = 2; qkv.out_mode[2] = 3;
    gemm_f16_kernel<<<dim3(DD / 128, MM / 128, 3), 128>>>(qkv);

    // attention (BQ=64)
    attn_f16_kernel<<<dim3(SS / 64, BB * HH), 128>>>();

    // output projection
    GemmArgs og;
    og.A[0] = (const __half*)p_ctxh; og.A[1] = og.A[0]; og.A[2] = og.A[0];
    og.W[0] = w3; og.W[1] = w3; og.W[2] = w3;
    og.bias[0] = wo_b; og.bias[1] = wo_b; og.bias[2] = wo_b;
    og.C = out;
    og.out_mode[0] = 0; og.out_mode[1] = 0; og.out_mode[2] = 0;
    gemm_f16_kernel<<<dim3(DD / 128, MM / 128, 1), 128>>>(og);
}